// round 15
// baseline (speedup 1.0000x reference)
#include <cuda_runtime.h>
#include <cstdint>

#define D        256
#define NCODES   1024
#define BM       128
#define BN       128
#define KC       32
#define AS_STRIDE 264
#define BS_STRIDE 36
#define MAXROWS  65536
#define GATHER_BLOCKS 8192
#define MARGIN   0.12f
#define RROWS    32

__device__ float  g_cnorm[NCODES];
__device__ int    g_argmin[MAXROWS];
__device__ int    g_flagged[MAXROWS];
__device__ int    g_flagcnt;
__device__ double g_partial[GATHER_BLOCKS];

// ---------------------------------------------------------------------------
__device__ __forceinline__ uint32_t tf32r(float v) {
    uint32_t r;
    asm("cvt.rna.tf32.f32 %0, %1;" : "=r"(r) : "f"(v));
    return r;
}
__device__ __forceinline__ void mma8(float* d, const uint32_t* a,
                                     const uint32_t* b) {
    asm volatile(
        "mma.sync.aligned.m16n8k8.row.col.f32.tf32.tf32.f32 "
        "{%0,%1,%2,%3}, {%4,%5,%6,%7}, {%8,%9}, {%0,%1,%2,%3};"
        : "+f"(d[0]), "+f"(d[1]), "+f"(d[2]), "+f"(d[3])
        : "r"(a[0]), "r"(a[1]), "r"(a[2]), "r"(a[3]), "r"(b[0]), "r"(b[1]));
}

// ---------------------------------------------------------------------------
// Kernel 1: codebook norms (exact fp32) + reset flag counter
// ---------------------------------------------------------------------------
__global__ void norms_kernel(const float* __restrict__ cb) {
    int k = blockIdx.x;
    int lane = threadIdx.x;
    if (k == 0 && lane == 0) g_flagcnt = 0;
    const float4* row = reinterpret_cast<const float4*>(cb + (size_t)k * D);
    float s = 0.f;
#pragma unroll
    for (int i = 0; i < 2; i++) {
        float4 v = row[lane + 32 * i];
        s += v.x * v.x + v.y * v.y + v.z * v.z + v.w * v.w;
    }
#pragma unroll
    for (int off = 16; off > 0; off >>= 1)
        s += __shfl_xor_sync(0xffffffffu, s, off);
    if (lane == 0) g_cnorm[k] = s;
}

// ---------------------------------------------------------------------------
// Kernel 2 (pass A): single-pass tf32 GEMM, per-row top-2 + argmin + flagging.
// (round-8/14 structure: lean top-2 tracking, mma-pipe-bound)
// ---------------------------------------------------------------------------
extern __shared__ float dynsmem[];
#define SMEM_BYTES ((BM * AS_STRIDE + BN * BS_STRIDE) * 4)

__global__ __launch_bounds__(256)
void argmin_kernel(const float* __restrict__ x, const float* __restrict__ cb) {
    float* As = dynsmem;                       // [128][264] tf32-rounded
    float* Bs = dynsmem + BM * AS_STRIDE;      // [128][36]  tf32-rounded
    __shared__ float tv1[BM][4];
    __shared__ float tv2[BM][4];
    __shared__ int   ti1[BM][4];

    int tid  = threadIdx.x;
    int wid  = tid >> 5;
    int lane = tid & 31;
    int g    = lane >> 2;
    int tig  = lane & 3;
    int wm   = wid & 1;
    int wn   = wid >> 1;
    int m0   = blockIdx.x * BM;

    const float4* x4  = reinterpret_cast<const float4*>(x);
    const float4* cb4 = reinterpret_cast<const float4*>(cb);

    // ---- stage full A row-block once, tf32-rounded ----
#pragma unroll
    for (int it = 0; it < 32; it++) {
        int i  = tid + it * 256;
        int r  = i >> 6;
        int c4 = i & 63;
        float4 v = x4[(size_t)(m0 + r) * 64 + c4];
        float* dst = As + r * AS_STRIDE + c4 * 4;
        dst[0] = __uint_as_float(tf32r(v.x));
        dst[1] = __uint_as_float(tf32r(v.y));
        dst[2] = __uint_as_float(tf32r(v.z));
        dst[3] = __uint_as_float(tf32r(v.w));
    }

    float b1[8], b2[8];
    int   i1[8];
#pragma unroll
    for (int i = 0; i < 8; i++) { b1[i] = 3.4e38f; b2[i] = 3.4e38f; i1[i] = 0; }

    for (int nc = 0; nc < NCODES / BN; nc++) {
        float acc[4][4][4];
#pragma unroll
        for (int mi = 0; mi < 4; mi++)
#pragma unroll
            for (int ni = 0; ni < 4; ni++)
#pragma unroll
                for (int r = 0; r < 4; r++) acc[mi][ni][r] = 0.f;

        for (int kc = 0; kc < D / KC; kc++) {
            __syncthreads();
#pragma unroll
            for (int it = 0; it < 4; it++) {
                int i  = tid + it * 256;
                int r  = i >> 3;
                int c4 = i & 7;
                float4 v = cb4[(size_t)(nc * BN + r) * 64 + kc * 8 + c4];
                float* dst = Bs + r * BS_STRIDE + c4 * 4;
                dst[0] = __uint_as_float(tf32r(v.x));
                dst[1] = __uint_as_float(tf32r(v.y));
                dst[2] = __uint_as_float(tf32r(v.z));
                dst[3] = __uint_as_float(tf32r(v.w));
            }
            __syncthreads();

#pragma unroll
            for (int ks = 0; ks < 4; ks++) {
                int kk = kc * KC + ks * 8;
                uint32_t af[4][4];
#pragma unroll
                for (int mi = 0; mi < 4; mi++) {
                    int ar = wm * 64 + mi * 16;
                    af[mi][0] = __float_as_uint(As[(ar + g)     * AS_STRIDE + kk + tig]);
                    af[mi][1] = __float_as_uint(As[(ar + g + 8) * AS_STRIDE + kk + tig]);
                    af[mi][2] = __float_as_uint(As[(ar + g)     * AS_STRIDE + kk + tig + 4]);
                    af[mi][3] = __float_as_uint(As[(ar + g + 8) * AS_STRIDE + kk + tig + 4]);
                }
                uint32_t bf[4][2];
#pragma unroll
                for (int ni = 0; ni < 4; ni++) {
                    int br = wn * 32 + ni * 8;
                    bf[ni][0] = __float_as_uint(Bs[(br + g) * BS_STRIDE + ks * 8 + tig]);
                    bf[ni][1] = __float_as_uint(Bs[(br + g) * BS_STRIDE + ks * 8 + tig + 4]);
                }
#pragma unroll
                for (int mi = 0; mi < 4; mi++)
#pragma unroll
                    for (int ni = 0; ni < 4; ni++)
                        mma8(acc[mi][ni], af[mi], bf[ni]);
            }
        }

        // ---- top-2 + argmin update ----
#pragma unroll
        for (int mi = 0; mi < 4; mi++)
#pragma unroll
            for (int h = 0; h < 2; h++) {
                int bi_ = mi * 2 + h;
#pragma unroll
                for (int ni = 0; ni < 4; ni++)
#pragma unroll
                    for (int q = 0; q < 2; q++) {
                        int code = nc * BN + wn * 32 + ni * 8 + 2 * tig + q;
                        float s = g_cnorm[code] - 2.f * acc[mi][ni][h * 2 + q];
                        if (s < b1[bi_] || (s == b1[bi_] && code < i1[bi_])) {
                            b2[bi_] = b1[bi_];
                            b1[bi_] = s;
                            i1[bi_] = code;
                        } else if (s < b2[bi_]) {
                            b2[bi_] = s;
                        }
                    }
            }
    }

    // ---- merge across quad (tig) ----
#pragma unroll
    for (int i = 0; i < 8; i++) {
#pragma unroll
        for (int t = 1; t < 4; t <<= 1) {
            float ob1 = __shfl_xor_sync(0xffffffffu, b1[i], t);
            int   oi1 = __shfl_xor_sync(0xffffffffu, i1[i], t);
            float ob2 = __shfl_xor_sync(0xffffffffu, b2[i], t);
            if (ob1 < b1[i] || (ob1 == b1[i] && oi1 < i1[i])) {
                b2[i] = fminf(b1[i], ob2);
                b1[i] = ob1;
                i1[i] = oi1;
            } else {
                b2[i] = fminf(b2[i], ob1);
            }
        }
    }
    // ---- merge across 4 N-warps ----
    if (tig == 0) {
#pragma unroll
        for (int mi = 0; mi < 4; mi++)
#pragma unroll
            for (int h = 0; h < 2; h++) {
                int row = wm * 64 + mi * 16 + h * 8 + g;
                tv1[row][wn] = b1[mi * 2 + h];
                tv2[row][wn] = b2[mi * 2 + h];
                ti1[row][wn] = i1[mi * 2 + h];
            }
    }
    __syncthreads();
    if (tid < BM) {
        float fb1 = tv1[tid][0], fb2 = tv2[tid][0];
        int   fi1 = ti1[tid][0];
#pragma unroll
        for (int w = 1; w < 4; w++) {
            float ob1 = tv1[tid][w], ob2 = tv2[tid][w];
            int   oi1 = ti1[tid][w];
            if (ob1 < fb1 || (ob1 == fb1 && oi1 < fi1)) {
                fb2 = fminf(fb1, ob2);
                fb1 = ob1;
                fi1 = oi1;
            } else {
                fb2 = fminf(fb2, ob1);
            }
        }
        g_argmin[m0 + tid] = fi1;
        if (fb2 - fb1 < MARGIN) {
            int p = atomicAdd(&g_flagcnt, 1);
            g_flagged[p] = m0 + tid;
        }
    }
}

// ---------------------------------------------------------------------------
// Kernel 2b: exact fp32 rescore of flagged rows (full 1024-code scan).
// 32 rows per CTA; aggregate-FLOP-bound, grid sized so all tiles resident.
// ---------------------------------------------------------------------------
__global__ __launch_bounds__(256)
void rescore_kernel(const float* __restrict__ x, const float* __restrict__ cb) {
    __shared__ float xs[RROWS][260];
    __shared__ int   rowid[RROWS];
    __shared__ float wv[8][8];
    __shared__ int   wi_[8][8];

    int tid  = threadIdx.x;
    int lane = tid & 31;
    int warp = tid >> 5;
    int tr   = tid >> 6;
    int tc   = tid & 63;
    int cnt  = g_flagcnt;

    const float4* x4  = reinterpret_cast<const float4*>(x);
    const float4* cb4 = reinterpret_cast<const float4*>(cb);

    for (int base = blockIdx.x * RROWS; base < cnt; base += gridDim.x * RROWS) {
        if (tid < RROWS)
            rowid[tid] = (base + tid < cnt) ? g_flagged[base + tid] : -1;
        __syncthreads();
        for (int i = tid; i < RROWS * 64; i += 256) {
            int r  = i >> 6;
            int c4 = i & 63;
            int row = rowid[r];
            if (row >= 0) {
                float4 v = x4[(size_t)row * 64 + c4];
                *reinterpret_cast<float4*>(&xs[r][c4 * 4]) = v;
            }
        }
        __syncthreads();

        float rb[8];
        int   ri_[8];
#pragma unroll
        for (int r = 0; r < 8; r++) { rb[r] = 3.4e38f; ri_[r] = 0; }

        for (int j = 0; j < 4; j++) {
            int c0 = j * 256 + tc * 4;
            float acc[8][4];
#pragma unroll
            for (int r = 0; r < 8; r++)
#pragma unroll
                for (int q = 0; q < 4; q++) acc[r][q] = 0.f;
#pragma unroll 4
            for (int d4 = 0; d4 < 64; d4++) {
                float4 e[4];
#pragma unroll
                for (int q = 0; q < 4; q++)
                    e[q] = cb4[(size_t)(c0 + q) * 64 + d4];
#pragma unroll
                for (int r = 0; r < 8; r++) {
                    float4 xv = *reinterpret_cast<const float4*>(
                        &xs[tr * 8 + r][d4 * 4]);
#pragma unroll
                    for (int q = 0; q < 4; q++)
                        acc[r][q] += xv.x * e[q].x + xv.y * e[q].y +
                                     xv.z * e[q].z + xv.w * e[q].w;
                }
            }
#pragma unroll
            for (int q = 0; q < 4; q++) {
                int code = c0 + q;
                float cn = g_cnorm[code];
#pragma unroll
                for (int r = 0; r < 8; r++) {
                    float s = cn - 2.f * acc[r][q];
                    if (s < rb[r] || (s == rb[r] && code < ri_[r])) {
                        rb[r] = s;
                        ri_[r] = code;
                    }
                }
            }
        }

        // warp lex-min reduce (all lanes same tr -> same rows)
#pragma unroll
        for (int r = 0; r < 8; r++) {
#pragma unroll
            for (int t = 1; t < 32; t <<= 1) {
                float os = __shfl_xor_sync(0xffffffffu, rb[r], t);
                int   oi = __shfl_xor_sync(0xffffffffu, ri_[r], t);
                if (os < rb[r] || (os == rb[r] && oi < ri_[r])) {
                    rb[r] = os;
                    ri_[r] = oi;
                }
            }
        }
        if (lane == 0)
#pragma unroll
            for (int r = 0; r < 8; r++) { wv[warp][r] = rb[r]; wi_[warp][r] = ri_[r]; }
        __syncthreads();
        if (tid < RROWS) {
            int trr = tid >> 3, l8 = tid & 7;
            float a = wv[2 * trr][l8];
            int   ai = wi_[2 * trr][l8];
            float b = wv[2 * trr + 1][l8];
            int   bi = wi_[2 * trr + 1][l8];
            if (b < a || (b == a && bi < ai)) { a = b; ai = bi; }
            int row = rowid[tid];
            if (row >= 0) g_argmin[row] = ai;
        }
        __syncthreads();
    }
}

// ---------------------------------------------------------------------------
// Kernel 3: gather quantized = codebook[argmin], accumulate sum((q-x)^2)
// ---------------------------------------------------------------------------
__global__ __launch_bounds__(256)
void gather_kernel(const float* __restrict__ x, const float* __restrict__ cb,
                   float* __restrict__ out, int nrows) {
    __shared__ float warp_s[8];
    int lane = threadIdx.x & 31;
    int wip  = threadIdx.x >> 5;
    int row  = blockIdx.x * 8 + wip;

    float s = 0.f;
    if (row < nrows) {
        int idx = g_argmin[row];
        const float4* q4 = reinterpret_cast<const float4*>(cb + (size_t)idx * D);
        const float4* xr = reinterpret_cast<const float4*>(x + (size_t)row * D);
        float4* o4 = reinterpret_cast<float4*>(out) + (size_t)row * (D / 4);
#pragma unroll
        for (int t = 0; t < 2; t++) {
            int p = lane + 32 * t;
            float4 q  = q4[p];
            float4 xv = xr[p];
            o4[p] = q;
            float dx = q.x - xv.x, dy = q.y - xv.y;
            float dz = q.z - xv.z, dw = q.w - xv.w;
            s += dx * dx + dy * dy + dz * dz + dw * dw;
        }
    }
#pragma unroll
    for (int off = 16; off > 0; off >>= 1)
        s += __shfl_xor_sync(0xffffffffu, s, off);
    if (lane == 0) warp_s[wip] = s;
    __syncthreads();
    if (threadIdx.x == 0) {
        double tot = 0.0;
#pragma unroll
        for (int w = 0; w < 8; w++) tot += (double)warp_s[w];
        g_partial[blockIdx.x] = tot;
    }
}

// ---------------------------------------------------------------------------
// Kernel 4: final loss reduction (deterministic)
// ---------------------------------------------------------------------------
__global__ void loss_kernel(float* __restrict__ loss_out, int nblocks,
                            float inv_nd) {
    __shared__ double sh[256];
    double s = 0.0;
    for (int i = threadIdx.x; i < nblocks; i += 256) s += g_partial[i];
    sh[threadIdx.x] = s;
    __syncthreads();
    for (int off = 128; off > 0; off >>= 1) {
        if (threadIdx.x < off) sh[threadIdx.x] += sh[threadIdx.x + off];
        __syncthreads();
    }
    if (threadIdx.x == 0)
        *loss_out = (float)(1.25 * sh[0] * (double)inv_nd);
}

// ---------------------------------------------------------------------------
extern "C" void kernel_launch(void* const* d_in, const int* in_sizes, int n_in,
                              void* d_out, int out_size) {
    const float* x  = (const float*)d_in[0];
    const float* cb = (const float*)d_in[1];
    float* out = (float*)d_out;

    int n     = in_sizes[0];       // 16777216
    int nrows = n / D;             // 65536

    cudaFuncSetAttribute(argmin_kernel,
                         cudaFuncAttributeMaxDynamicSharedMemorySize,
                         SMEM_BYTES);

    norms_kernel<<<NCODES, 32>>>(cb);
    argmin_kernel<<<nrows / BM, 256, SMEM_BYTES>>>(x, cb);
    rescore_kernel<<<592, 256>>>(x, cb);

    int gblocks = (nrows + 7) / 8;      // 8192
    gather_kernel<<<gblocks, 256>>>(x, cb, out, nrows);
    loss_kernel<<<1, 256>>>(out + (out_size - 1), gblocks, 1.0f / (float)n);
}

// round 16
// speedup vs baseline: 1.5442x; 1.5442x over previous
#include <cuda_runtime.h>
#include <cstdint>

#define D        256
#define NCODES   1024
#define BM       128
#define BN       128
#define KC       32
#define AS_STRIDE 264
#define BS_STRIDE 36
#define MAXROWS  65536
#define GATHER_BLOCKS 8192
#define MARGIN   0.12f
#define RROWS    32

__device__ float  g_cnorm[NCODES];
__device__ int    g_argmin[MAXROWS];
__device__ int    g_flagged[MAXROWS];
__device__ int    g_flagcnt;
__device__ double g_partial[GATHER_BLOCKS];

// ---------------------------------------------------------------------------
__device__ __forceinline__ uint32_t tf32r(float v) {
    uint32_t r;
    asm("cvt.rna.tf32.f32 %0, %1;" : "=r"(r) : "f"(v));
    return r;
}
__device__ __forceinline__ void mma8(float* d, const uint32_t* a,
                                     const uint32_t* b) {
    asm volatile(
        "mma.sync.aligned.m16n8k8.row.col.f32.tf32.tf32.f32 "
        "{%0,%1,%2,%3}, {%4,%5,%6,%7}, {%8,%9}, {%0,%1,%2,%3};"
        : "+f"(d[0]), "+f"(d[1]), "+f"(d[2]), "+f"(d[3])
        : "r"(a[0]), "r"(a[1]), "r"(a[2]), "r"(a[3]), "r"(b[0]), "r"(b[1]));
}

// ---------------------------------------------------------------------------
// Kernel 1: codebook norms (exact fp32) + reset flag counter
// ---------------------------------------------------------------------------
__global__ void norms_kernel(const float* __restrict__ cb) {
    int k = blockIdx.x;
    int lane = threadIdx.x;
    if (k == 0 && lane == 0) g_flagcnt = 0;
    const float4* row = reinterpret_cast<const float4*>(cb + (size_t)k * D);
    float s = 0.f;
#pragma unroll
    for (int i = 0; i < 2; i++) {
        float4 v = row[lane + 32 * i];
        s += v.x * v.x + v.y * v.y + v.z * v.z + v.w * v.w;
    }
#pragma unroll
    for (int off = 16; off > 0; off >>= 1)
        s += __shfl_xor_sync(0xffffffffu, s, off);
    if (lane == 0) g_cnorm[k] = s;
}

// ---------------------------------------------------------------------------
// Kernel 2 (pass A): single-pass tf32 GEMM, per-row top-2 + argmin + flagging.
// (round-8/14 structure: lean top-2 tracking, mma-pipe-bound)
// ---------------------------------------------------------------------------
extern __shared__ float dynsmem[];
#define SMEM_BYTES ((BM * AS_STRIDE + BN * BS_STRIDE) * 4)

__global__ __launch_bounds__(256)
void argmin_kernel(const float* __restrict__ x, const float* __restrict__ cb) {
    float* As = dynsmem;                       // [128][264] tf32-rounded
    float* Bs = dynsmem + BM * AS_STRIDE;      // [128][36]  tf32-rounded
    __shared__ float tv1[BM][4];
    __shared__ float tv2[BM][4];
    __shared__ int   ti1[BM][4];

    int tid  = threadIdx.x;
    int wid  = tid >> 5;
    int lane = tid & 31;
    int g    = lane >> 2;
    int tig  = lane & 3;
    int wm   = wid & 1;
    int wn   = wid >> 1;
    int m0   = blockIdx.x * BM;

    const float4* x4  = reinterpret_cast<const float4*>(x);
    const float4* cb4 = reinterpret_cast<const float4*>(cb);

    // ---- stage full A row-block once, tf32-rounded ----
#pragma unroll
    for (int it = 0; it < 32; it++) {
        int i  = tid + it * 256;
        int r  = i >> 6;
        int c4 = i & 63;
        float4 v = x4[(size_t)(m0 + r) * 64 + c4];
        float* dst = As + r * AS_STRIDE + c4 * 4;
        dst[0] = __uint_as_float(tf32r(v.x));
        dst[1] = __uint_as_float(tf32r(v.y));
        dst[2] = __uint_as_float(tf32r(v.z));
        dst[3] = __uint_as_float(tf32r(v.w));
    }

    float b1[8], b2[8];
    int   i1[8];
#pragma unroll
    for (int i = 0; i < 8; i++) { b1[i] = 3.4e38f; b2[i] = 3.4e38f; i1[i] = 0; }

    for (int nc = 0; nc < NCODES / BN; nc++) {
        float acc[4][4][4];
#pragma unroll
        for (int mi = 0; mi < 4; mi++)
#pragma unroll
            for (int ni = 0; ni < 4; ni++)
#pragma unroll
                for (int r = 0; r < 4; r++) acc[mi][ni][r] = 0.f;

        for (int kc = 0; kc < D / KC; kc++) {
            __syncthreads();
#pragma unroll
            for (int it = 0; it < 4; it++) {
                int i  = tid + it * 256;
                int r  = i >> 3;
                int c4 = i & 7;
                float4 v = cb4[(size_t)(nc * BN + r) * 64 + kc * 8 + c4];
                float* dst = Bs + r * BS_STRIDE + c4 * 4;
                dst[0] = __uint_as_float(tf32r(v.x));
                dst[1] = __uint_as_float(tf32r(v.y));
                dst[2] = __uint_as_float(tf32r(v.z));
                dst[3] = __uint_as_float(tf32r(v.w));
            }
            __syncthreads();

#pragma unroll
            for (int ks = 0; ks < 4; ks++) {
                int kk = kc * KC + ks * 8;
                uint32_t af[4][4];
#pragma unroll
                for (int mi = 0; mi < 4; mi++) {
                    int ar = wm * 64 + mi * 16;
                    af[mi][0] = __float_as_uint(As[(ar + g)     * AS_STRIDE + kk + tig]);
                    af[mi][1] = __float_as_uint(As[(ar + g + 8) * AS_STRIDE + kk + tig]);
                    af[mi][2] = __float_as_uint(As[(ar + g)     * AS_STRIDE + kk + tig + 4]);
                    af[mi][3] = __float_as_uint(As[(ar + g + 8) * AS_STRIDE + kk + tig + 4]);
                }
                uint32_t bf[4][2];
#pragma unroll
                for (int ni = 0; ni < 4; ni++) {
                    int br = wn * 32 + ni * 8;
                    bf[ni][0] = __float_as_uint(Bs[(br + g) * BS_STRIDE + ks * 8 + tig]);
                    bf[ni][1] = __float_as_uint(Bs[(br + g) * BS_STRIDE + ks * 8 + tig + 4]);
                }
#pragma unroll
                for (int mi = 0; mi < 4; mi++)
#pragma unroll
                    for (int ni = 0; ni < 4; ni++)
                        mma8(acc[mi][ni], af[mi], bf[ni]);
            }
        }

        // ---- top-2 + argmin update ----
#pragma unroll
        for (int mi = 0; mi < 4; mi++)
#pragma unroll
            for (int h = 0; h < 2; h++) {
                int bi_ = mi * 2 + h;
#pragma unroll
                for (int ni = 0; ni < 4; ni++)
#pragma unroll
                    for (int q = 0; q < 2; q++) {
                        int code = nc * BN + wn * 32 + ni * 8 + 2 * tig + q;
                        float s = g_cnorm[code] - 2.f * acc[mi][ni][h * 2 + q];
                        if (s < b1[bi_] || (s == b1[bi_] && code < i1[bi_])) {
                            b2[bi_] = b1[bi_];
                            b1[bi_] = s;
                            i1[bi_] = code;
                        } else if (s < b2[bi_]) {
                            b2[bi_] = s;
                        }
                    }
            }
    }

    // ---- merge across quad (tig) ----
#pragma unroll
    for (int i = 0; i < 8; i++) {
#pragma unroll
        for (int t = 1; t < 4; t <<= 1) {
            float ob1 = __shfl_xor_sync(0xffffffffu, b1[i], t);
            int   oi1 = __shfl_xor_sync(0xffffffffu, i1[i], t);
            float ob2 = __shfl_xor_sync(0xffffffffu, b2[i], t);
            if (ob1 < b1[i] || (ob1 == b1[i] && oi1 < i1[i])) {
                b2[i] = fminf(b1[i], ob2);
                b1[i] = ob1;
                i1[i] = oi1;
            } else {
                b2[i] = fminf(b2[i], ob1);
            }
        }
    }
    // ---- merge across 4 N-warps ----
    if (tig == 0) {
#pragma unroll
        for (int mi = 0; mi < 4; mi++)
#pragma unroll
            for (int h = 0; h < 2; h++) {
                int row = wm * 64 + mi * 16 + h * 8 + g;
                tv1[row][wn] = b1[mi * 2 + h];
                tv2[row][wn] = b2[mi * 2 + h];
                ti1[row][wn] = i1[mi * 2 + h];
            }
    }
    __syncthreads();
    if (tid < BM) {
        float fb1 = tv1[tid][0], fb2 = tv2[tid][0];
        int   fi1 = ti1[tid][0];
#pragma unroll
        for (int w = 1; w < 4; w++) {
            float ob1 = tv1[tid][w], ob2 = tv2[tid][w];
            int   oi1 = ti1[tid][w];
            if (ob1 < fb1 || (ob1 == fb1 && oi1 < fi1)) {
                fb2 = fminf(fb1, ob2);
                fb1 = ob1;
                fi1 = oi1;
            } else {
                fb2 = fminf(fb2, ob1);
            }
        }
        g_argmin[m0 + tid] = fi1;
        if (fb2 - fb1 < MARGIN) {
            int p = atomicAdd(&g_flagcnt, 1);
            g_flagged[p] = m0 + tid;
        }
    }
}

// ---------------------------------------------------------------------------
// Kernel 2b: exact fp32 rescore of flagged rows (full 1024-code scan).
// 32 rows per CTA; aggregate-FLOP-bound, grid sized so all tiles resident.
// ---------------------------------------------------------------------------
__global__ __launch_bounds__(256)
void rescore_kernel(const float* __restrict__ x, const float* __restrict__ cb) {
    __shared__ float xs[RROWS][260];
    __shared__ int   rowid[RROWS];
    __shared__ float wv[8][8];
    __shared__ int   wi_[8][8];

    int tid  = threadIdx.x;
    int lane = tid & 31;
    int warp = tid >> 5;
    int tr   = tid >> 6;
    int tc   = tid & 63;
    int cnt  = g_flagcnt;

    const float4* x4  = reinterpret_cast<const float4*>(x);
    const float4* cb4 = reinterpret_cast<const float4*>(cb);

    for (int base = blockIdx.x * RROWS; base < cnt; base += gridDim.x * RROWS) {
        if (tid < RROWS)
            rowid[tid] = (base + tid < cnt) ? g_flagged[base + tid] : -1;
        __syncthreads();
        for (int i = tid; i < RROWS * 64; i += 256) {
            int r  = i >> 6;
            int c4 = i & 63;
            int row = rowid[r];
            if (row >= 0) {
                float4 v = x4[(size_t)row * 64 + c4];
                *reinterpret_cast<float4*>(&xs[r][c4 * 4]) = v;
            }
        }
        __syncthreads();

        float rb[8];
        int   ri_[8];
#pragma unroll
        for (int r = 0; r < 8; r++) { rb[r] = 3.4e38f; ri_[r] = 0; }

        for (int j = 0; j < 4; j++) {
            int c0 = j * 256 + tc * 4;
            float acc[8][4];
#pragma unroll
            for (int r = 0; r < 8; r++)
#pragma unroll
                for (int q = 0; q < 4; q++) acc[r][q] = 0.f;
#pragma unroll 4
            for (int d4 = 0; d4 < 64; d4++) {
                float4 e[4];
#pragma unroll
                for (int q = 0; q < 4; q++)
                    e[q] = cb4[(size_t)(c0 + q) * 64 + d4];
#pragma unroll
                for (int r = 0; r < 8; r++) {
                    float4 xv = *reinterpret_cast<const float4*>(
                        &xs[tr * 8 + r][d4 * 4]);
#pragma unroll
                    for (int q = 0; q < 4; q++)
                        acc[r][q] += xv.x * e[q].x + xv.y * e[q].y +
                                     xv.z * e[q].z + xv.w * e[q].w;
                }
            }
#pragma unroll
            for (int q = 0; q < 4; q++) {
                int code = c0 + q;
                float cn = g_cnorm[code];
#pragma unroll
                for (int r = 0; r < 8; r++) {
                    float s = cn - 2.f * acc[r][q];
                    if (s < rb[r] || (s == rb[r] && code < ri_[r])) {
                        rb[r] = s;
                        ri_[r] = code;
                    }
                }
            }
        }

        // warp lex-min reduce (all lanes same tr -> same rows)
#pragma unroll
        for (int r = 0; r < 8; r++) {
#pragma unroll
            for (int t = 1; t < 32; t <<= 1) {
                float os = __shfl_xor_sync(0xffffffffu, rb[r], t);
                int   oi = __shfl_xor_sync(0xffffffffu, ri_[r], t);
                if (os < rb[r] || (os == rb[r] && oi < ri_[r])) {
                    rb[r] = os;
                    ri_[r] = oi;
                }
            }
        }
        if (lane == 0)
#pragma unroll
            for (int r = 0; r < 8; r++) { wv[warp][r] = rb[r]; wi_[warp][r] = ri_[r]; }
        __syncthreads();
        if (tid < RROWS) {
            int trr = tid >> 3, l8 = tid & 7;
            float a = wv[2 * trr][l8];
            int   ai = wi_[2 * trr][l8];
            float b = wv[2 * trr + 1][l8];
            int   bi = wi_[2 * trr + 1][l8];
            if (b < a || (b == a && bi < ai)) { a = b; ai = bi; }
            int row = rowid[tid];
            if (row >= 0) g_argmin[row] = ai;
        }
        __syncthreads();
    }
}

// ---------------------------------------------------------------------------
// Kernel 3: gather quantized = codebook[argmin], accumulate sum((q-x)^2)
// ---------------------------------------------------------------------------
__global__ __launch_bounds__(256)
void gather_kernel(const float* __restrict__ x, const float* __restrict__ cb,
                   float* __restrict__ out, int nrows) {
    __shared__ float warp_s[8];
    int lane = threadIdx.x & 31;
    int wip  = threadIdx.x >> 5;
    int row  = blockIdx.x * 8 + wip;

    float s = 0.f;
    if (row < nrows) {
        int idx = g_argmin[row];
        const float4* q4 = reinterpret_cast<const float4*>(cb + (size_t)idx * D);
        const float4* xr = reinterpret_cast<const float4*>(x + (size_t)row * D);
        float4* o4 = reinterpret_cast<float4*>(out) + (size_t)row * (D / 4);
#pragma unroll
        for (int t = 0; t < 2; t++) {
            int p = lane + 32 * t;
            float4 q  = q4[p];
            float4 xv = xr[p];
            o4[p] = q;
            float dx = q.x - xv.x, dy = q.y - xv.y;
            float dz = q.z - xv.z, dw = q.w - xv.w;
            s += dx * dx + dy * dy + dz * dz + dw * dw;
        }
    }
#pragma unroll
    for (int off = 16; off > 0; off >>= 1)
        s += __shfl_xor_sync(0xffffffffu, s, off);
    if (lane == 0) warp_s[wip] = s;
    __syncthreads();
    if (threadIdx.x == 0) {
        double tot = 0.0;
#pragma unroll
        for (int w = 0; w < 8; w++) tot += (double)warp_s[w];
        g_partial[blockIdx.x] = tot;
    }
}

// ---------------------------------------------------------------------------
// Kernel 4: final loss reduction (deterministic)
// ---------------------------------------------------------------------------
__global__ void loss_kernel(float* __restrict__ loss_out, int nblocks,
                            float inv_nd) {
    __shared__ double sh[256];
    double s = 0.0;
    for (int i = threadIdx.x; i < nblocks; i += 256) s += g_partial[i];
    sh[threadIdx.x] = s;
    __syncthreads();
    for (int off = 128; off > 0; off >>= 1) {
        if (threadIdx.x < off) sh[threadIdx.x] += sh[threadIdx.x + off];
        __syncthreads();
    }
    if (threadIdx.x == 0)
        *loss_out = (float)(1.25 * sh[0] * (double)inv_nd);
}

// ---------------------------------------------------------------------------
extern "C" void kernel_launch(void* const* d_in, const int* in_sizes, int n_in,
                              void* d_out, int out_size) {
    const float* x  = (const float*)d_in[0];
    const float* cb = (const float*)d_in[1];
    float* out = (float*)d_out;

    int n     = in_sizes[0];       // 16777216
    int nrows = n / D;             // 65536

    cudaFuncSetAttribute(argmin_kernel,
                         cudaFuncAttributeMaxDynamicSharedMemorySize,
                         SMEM_BYTES);

    norms_kernel<<<NCODES, 32>>>(cb);
    argmin_kernel<<<nrows / BM, 256, SMEM_BYTES>>>(x, cb);
    rescore_kernel<<<592, 256>>>(x, cb);

    int gblocks = (nrows + 7) / 8;      // 8192
    gather_kernel<<<gblocks, 256>>>(x, cb, out, nrows);
    loss_kernel<<<1, 256>>>(out + (out_size - 1), gblocks, 1.0f / (float)n);
}